// round 1
// baseline (speedup 1.0000x reference)
#include <cuda_runtime.h>
#include <math.h>

#define BN 4
#define TT 1024
#define NTOK 4096          // B*T
#define SWc 96
#define FBc 64
#define Fc 6144            // SW*FB
#define EMBc 512
#define Hc 3
#define DHc 32
#define FFc 384

// ---------------- scratch (static device globals; no allocs) ----------------
__device__ float  g_mid[(size_t)NTOK * Fc];    // (B,T,F) intermediate
__device__ float  g_emb[(size_t)NTOK * EMBc];  // (B,T,EMB) pre-norm
__device__ double g_part[256];                 // per-block sum / sumsq partials
__device__ float  g_stats[2];                  // mu, rstd

// ---------------- kernel 1: per-token rel-attention + FFN -------------------
#define XS 97      // row stride for 96-wide tiles (conflict-free)
#define SSx 65     // score row stride
#define ES 33      // Er row stride
#define HS 385     // hidden row stride

#define OFF_ATT 0          // 64*97 = 6208   (xs -> att_out -> staged output)
#define OFF_Q   6208       // 64*97
#define OFF_K   12416
#define OFF_V   18624      // ends 24832
#define OFF_HID 6208       // 64*385 = 24640, overlays Q/K/V (dead by FFN), ends 30848
#define OFF_W   30848      // 12288 floats: W stage / er+S+R / FFN weight tiles
#define SMEM_FLOATS 43136  // 172544 bytes

__global__ __launch_bounds__(256) void attn_ffn_kernel(
    const float* __restrict__ x,
    const float* __restrict__ Wq, const float* __restrict__ bq,
    const float* __restrict__ Wk, const float* __restrict__ bk,
    const float* __restrict__ Wv, const float* __restrict__ bv,
    const float* __restrict__ Er,
    const float* __restrict__ W1, const float* __restrict__ b1,
    const float* __restrict__ W2, const float* __restrict__ b2)
{
    extern __shared__ float sm[];
    float* s_att = sm + OFF_ATT;
    float* s_q   = sm + OFF_Q;
    float* s_k   = sm + OFF_K;
    float* s_v   = sm + OFF_V;
    float* s_hid = sm + OFF_HID;
    float* s_w   = sm + OFF_W;
    float* s_er  = s_w + 9216;   // survives QKV staging (staging uses [0,9216))
    float* s_S   = s_w;          // attention phase only (W stage dead)
    float* s_R   = s_w + 4160;

    const int tid = threadIdx.x;
    const int n   = blockIdx.x;
    const size_t base = (size_t)n * Fc;

    // xr[l][d] = x[n, d*FB + l]  (reshape(SW,FB) then transpose)
    for (int idx = tid; idx < Fc; idx += 256) {
        int d = idx >> 6, l = idx & 63;
        s_att[l * XS + d] = x[base + idx];
    }
    for (int idx = tid; idx < 64 * 32; idx += 256) {
        int j = idx >> 5, d = idx & 31;
        s_er[j * ES + d] = Er[idx];
    }
    __syncthreads();

    // ---- QKV projections: (64x96) @ (96x96) with W staged in smem ----
    const float* Wmats[3] = {Wq, Wk, Wv};
    const float* bvecs[3] = {bq, bk, bv};
    float* qkv[3] = {s_q, s_k, s_v};
    const int r0a = (tid >> 4) * 4;   // 16 row groups * 4
    const int c0a = (tid & 15) * 6;   // 16 col groups * 6
    for (int w = 0; w < 3; ++w) {
        const float* W = Wmats[w];
        for (int idx = tid; idx < 9216; idx += 256) s_w[idx] = W[idx];
        __syncthreads();
        float acc[4][6];
        #pragma unroll
        for (int r = 0; r < 4; ++r)
            #pragma unroll
            for (int c = 0; c < 6; ++c) acc[r][c] = 0.f;
        #pragma unroll 4
        for (int i = 0; i < 96; ++i) {
            float xv[4];
            #pragma unroll
            for (int r = 0; r < 4; ++r) xv[r] = s_att[(r0a + r) * XS + i];
            #pragma unroll
            for (int c = 0; c < 6; ++c) {
                float wv = s_w[i * 96 + c0a + c];
                #pragma unroll
                for (int r = 0; r < 4; ++r) acc[r][c] += xv[r] * wv;
            }
        }
        const float* bb = bvecs[w];
        float* o = qkv[w];
        #pragma unroll
        for (int r = 0; r < 4; ++r)
            #pragma unroll
            for (int c = 0; c < 6; ++c)
                o[(r0a + r) * XS + c0a + c] = acc[r][c] + bb[c0a + c];
        __syncthreads();
    }

    // ---- relative attention, per head ----
    const float scale = 0.17677669529663687f;   // 1/sqrt(32)
    const int wid = tid >> 5, lane = tid & 31;
    const int l0 = (tid >> 4) * 4, m0 = (tid & 15) * 4;
    const int oc0 = (tid & 15) * 2;
    for (int h = 0; h < 3; ++h) {
        const int hb = h * 32;
        float aS[4][4], aR[4][4];
        #pragma unroll
        for (int r = 0; r < 4; ++r)
            #pragma unroll
            for (int c = 0; c < 4; ++c) { aS[r][c] = 0.f; aR[r][c] = 0.f; }
        #pragma unroll 4
        for (int d = 0; d < 32; ++d) {
            float qv[4], kv[4], ev[4];
            #pragma unroll
            for (int r = 0; r < 4; ++r) qv[r] = s_q[(l0 + r) * XS + hb + d];
            #pragma unroll
            for (int c = 0; c < 4; ++c) kv[c] = s_k[(m0 + c) * XS + hb + d];
            #pragma unroll
            for (int c = 0; c < 4; ++c) ev[c] = s_er[(m0 + c) * ES + d];
            #pragma unroll
            for (int r = 0; r < 4; ++r)
                #pragma unroll
                for (int c = 0; c < 4; ++c) {
                    aS[r][c] += qv[r] * kv[c];
                    aR[r][c] += qv[r] * ev[c];
                }
        }
        #pragma unroll
        for (int r = 0; r < 4; ++r)
            #pragma unroll
            for (int c = 0; c < 4; ++c) {
                s_S[(l0 + r) * SSx + m0 + c] = aS[r][c];
                s_R[(l0 + r) * SSx + m0 + c] = aR[r][c];
            }
        __syncthreads();

        // softmax: warp per row; srel[l][m] = R[l][m+63-l] for m<=l
        for (int l = wid; l < 64; l += 8) {
            int m1 = lane + 32;
            float v0 = (lane <= l)
                ? (s_S[l * SSx + lane] + s_R[l * SSx + lane + 63 - l]) * scale : -1e30f;
            float v1 = (m1 <= l)
                ? (s_S[l * SSx + m1] + s_R[l * SSx + m1 + 63 - l]) * scale : -1e30f;
            float mx = fmaxf(v0, v1);
            #pragma unroll
            for (int o = 16; o; o >>= 1) mx = fmaxf(mx, __shfl_xor_sync(0xffffffffu, mx, o));
            float e0 = __expf(v0 - mx), e1 = __expf(v1 - mx);
            float ssum = e0 + e1;
            #pragma unroll
            for (int o = 16; o; o >>= 1) ssum += __shfl_xor_sync(0xffffffffu, ssum, o);
            float inv = 1.0f / ssum;
            s_S[l * SSx + lane] = e0 * inv;
            s_S[l * SSx + m1]   = e1 * inv;
        }
        __syncthreads();

        // O = P @ V (64x32 per head) -> att_out columns [hb, hb+32)
        float ao[4][2];
        #pragma unroll
        for (int r = 0; r < 4; ++r) { ao[r][0] = 0.f; ao[r][1] = 0.f; }
        #pragma unroll 4
        for (int m = 0; m < 64; ++m) {
            float pv[4], vv[2];
            #pragma unroll
            for (int r = 0; r < 4; ++r) pv[r] = s_S[(l0 + r) * SSx + m];
            #pragma unroll
            for (int c = 0; c < 2; ++c) vv[c] = s_v[m * XS + hb + oc0 + c];
            #pragma unroll
            for (int r = 0; r < 4; ++r)
                #pragma unroll
                for (int c = 0; c < 2; ++c) ao[r][c] += pv[r] * vv[c];
        }
        #pragma unroll
        for (int r = 0; r < 4; ++r)
            #pragma unroll
            for (int c = 0; c < 2; ++c)
                s_att[(l0 + r) * XS + hb + oc0 + c] = ao[r][c];
        __syncthreads();
    }

    // ---- FFN GEMM1: hid = relu(att(64x96) @ W1(96x384) + b1) ----
    const int fr0 = (tid >> 4) * 4;
    const int fc0 = (tid & 15) * 8;
    for (int jt = 0; jt < 3; ++jt) {
        __syncthreads();
        for (int idx = tid; idx < 12288; idx += 256) {
            int i = idx >> 7, c = idx & 127;
            s_w[idx] = W1[i * FFc + jt * 128 + c];
        }
        __syncthreads();
        float acc[4][8];
        #pragma unroll
        for (int r = 0; r < 4; ++r)
            #pragma unroll
            for (int c = 0; c < 8; ++c) acc[r][c] = 0.f;
        #pragma unroll 2
        for (int i = 0; i < 96; ++i) {
            float av[4];
            #pragma unroll
            for (int r = 0; r < 4; ++r) av[r] = s_att[(fr0 + r) * XS + i];
            float4 w0 = *(const float4*)&s_w[i * 128 + fc0];
            float4 w1 = *(const float4*)&s_w[i * 128 + fc0 + 4];
            float wb[8] = {w0.x, w0.y, w0.z, w0.w, w1.x, w1.y, w1.z, w1.w};
            #pragma unroll
            for (int r = 0; r < 4; ++r)
                #pragma unroll
                for (int c = 0; c < 8; ++c) acc[r][c] += av[r] * wb[c];
        }
        #pragma unroll
        for (int r = 0; r < 4; ++r)
            #pragma unroll
            for (int c = 0; c < 8; ++c)
                s_hid[(fr0 + r) * HS + jt * 128 + fc0 + c] =
                    fmaxf(acc[r][c] + b1[jt * 128 + fc0 + c], 0.f);
    }

    // ---- FFN GEMM2: out = hid(64x384) @ W2(384x96) + b2 ----
    const int gc0 = (tid & 15) * 6;
    float acc2[4][6];
    #pragma unroll
    for (int r = 0; r < 4; ++r)
        #pragma unroll
        for (int c = 0; c < 6; ++c) acc2[r][c] = 0.f;
    for (int kt = 0; kt < 3; ++kt) {
        __syncthreads();
        for (int idx = tid; idx < 12288; idx += 256)
            s_w[idx] = W2[kt * 12288 + idx];     // [128][96] tile
        __syncthreads();
        #pragma unroll 2
        for (int i = 0; i < 128; ++i) {
            float hv[4];
            #pragma unroll
            for (int r = 0; r < 4; ++r) hv[r] = s_hid[(fr0 + r) * HS + kt * 128 + i];
            #pragma unroll
            for (int c = 0; c < 6; ++c) {
                float wv = s_w[i * 96 + gc0 + c];
                #pragma unroll
                for (int r = 0; r < 4; ++r) acc2[r][c] += hv[r] * wv;
            }
        }
    }
    __syncthreads();
    #pragma unroll
    for (int r = 0; r < 4; ++r)
        #pragma unroll
        for (int c = 0; c < 6; ++c)
            s_att[(fr0 + r) * XS + gc0 + c] = acc2[r][c] + b2[gc0 + c];
    __syncthreads();
    // emb.transpose back: mid[n, d*64 + l] = out[l][d], coalesced store
    for (int idx = tid; idx < Fc; idx += 256) {
        int d = idx >> 6, l = idx & 63;
        g_mid[base + idx] = s_att[l * XS + d];
    }
}

// ---------------- kernel 2: (4096x6144)@(6144x512)+be, + stats partials -----
#define GBM 128
#define GBN 128
#define GBK 16

__global__ __launch_bounds__(256) void we_gemm_kernel(
    const float* __restrict__ We, const float* __restrict__ be)
{
    __shared__ float As[GBK * GBM];   // As[k][m] (transposed)
    __shared__ float Bs[GBK * GBN];   // Bs[k][c]
    __shared__ double red[16];

    const int tid = threadIdx.x;
    const int e0 = blockIdx.x * GBN;
    const int n0 = blockIdx.y * GBM;
    const int r0 = (tid >> 4) * 8;
    const int c0 = (tid & 15) * 8;

    float acc[8][8];
    #pragma unroll
    for (int i = 0; i < 8; ++i)
        #pragma unroll
        for (int j = 0; j < 8; ++j) acc[i][j] = 0.f;

    for (int k0 = 0; k0 < Fc; k0 += GBK) {
        __syncthreads();
        #pragma unroll
        for (int q = 0; q < 2; ++q) {                 // A: 128x16 via float4
            int idx = tid + q * 256;
            int m = idx >> 2, kq = (idx & 3) * 4;
            float4 v = *(const float4*)&g_mid[(size_t)(n0 + m) * Fc + k0 + kq];
            As[(kq + 0) * GBM + m] = v.x;
            As[(kq + 1) * GBM + m] = v.y;
            As[(kq + 2) * GBM + m] = v.z;
            As[(kq + 3) * GBM + m] = v.w;
        }
        #pragma unroll
        for (int q = 0; q < 8; ++q) {                 // B: 16x128 coalesced
            int idx = tid + q * 256;
            int k = idx >> 7, c = idx & 127;
            Bs[idx] = We[(size_t)(k0 + k) * EMBc + e0 + c];
        }
        __syncthreads();
        #pragma unroll
        for (int k = 0; k < GBK; ++k) {
            float4 a0 = *(const float4*)&As[k * GBM + r0];
            float4 a1 = *(const float4*)&As[k * GBM + r0 + 4];
            float4 b0 = *(const float4*)&Bs[k * GBN + c0];
            float4 b1 = *(const float4*)&Bs[k * GBN + c0 + 4];
            float a[8] = {a0.x, a0.y, a0.z, a0.w, a1.x, a1.y, a1.z, a1.w};
            float b[8] = {b0.x, b0.y, b0.z, b0.w, b1.x, b1.y, b1.z, b1.w};
            #pragma unroll
            for (int i = 0; i < 8; ++i)
                #pragma unroll
                for (int j = 0; j < 8; ++j) acc[i][j] += a[i] * b[j];
        }
    }

    double s = 0.0, s2 = 0.0;
    #pragma unroll
    for (int i = 0; i < 8; ++i)
        #pragma unroll
        for (int j = 0; j < 8; ++j) {
            float v = acc[i][j] + be[e0 + c0 + j];
            g_emb[(size_t)(n0 + r0 + i) * EMBc + e0 + c0 + j] = v;
            s  += (double)v;
            s2 += (double)v * (double)v;
        }
    #pragma unroll
    for (int o = 16; o; o >>= 1) {
        s  += __shfl_xor_sync(0xffffffffu, s, o);
        s2 += __shfl_xor_sync(0xffffffffu, s2, o);
    }
    const int wid = tid >> 5, lane = tid & 31;
    if (lane == 0) { red[wid] = s; red[wid + 8] = s2; }
    __syncthreads();
    if (tid == 0) {
        double ts = 0.0, ts2 = 0.0;
        #pragma unroll
        for (int i = 0; i < 8; ++i) { ts += red[i]; ts2 += red[i + 8]; }
        int bid = blockIdx.y * gridDim.x + blockIdx.x;   // < 128, deterministic slot
        g_part[bid * 2]     = ts;
        g_part[bid * 2 + 1] = ts2;
    }
}

// ---------------- kernel 3: finalize mean / rstd ----------------------------
__global__ void stats_kernel()
{
    if (threadIdx.x == 0) {
        double s = 0.0, s2 = 0.0;
        for (int i = 0; i < 128; ++i) { s += g_part[2 * i]; s2 += g_part[2 * i + 1]; }
        double cnt = (double)NTOK * (double)EMBc;
        double mu  = s / cnt;
        double var = s2 / cnt - mu * mu;
        g_stats[0] = (float)mu;
        g_stats[1] = (float)(1.0 / sqrt(var + 1e-8));
    }
}

// ---------------- kernel 4: normalize + segment means + residual ------------
__global__ __launch_bounds__(256) void final_kernel(
    const int* __restrict__ o_enc, const float* __restrict__ r_enc,
    float* __restrict__ out)
{
    const int n = blockIdx.x;
    const int b = n >> 10, t = n & 1023;
    __shared__ int s_len;
    if (threadIdx.x == 0) {
        int len = 0;
        bool is_start = (t == 0) || (o_enc[n] != 0);
        if (is_start) {
            int tt = t + 1;
            while (tt < TT && o_enc[b * TT + tt] == 0) ++tt;
            len = tt - t;
        }
        s_len = len;
    }
    __syncthreads();
    const float mu = g_stats[0], rs = g_stats[1];
    const int len = s_len;
    for (int e = threadIdx.x; e < EMBc; e += 256) {
        size_t bi = (size_t)n * EMBc + e;
        float v = (g_emb[bi] - mu) * rs;
        float o = v + r_enc[bi];
        if (len) {
            float sum = 0.f;
            for (int s = 0; s < len; ++s)
                sum += g_emb[(size_t)(n + s) * EMBc + e];
            o += (sum / (float)len - mu) * rs;   // mean of normalized values
        }
        out[bi] = o;
    }
}

// ---------------- launcher --------------------------------------------------
extern "C" void kernel_launch(void* const* d_in, const int* in_sizes, int n_in,
                              void* d_out, int out_size)
{
    const float* x     = (const float*)d_in[0];
    const int*   o_enc = (const int*)  d_in[1];
    const float* r_enc = (const float*)d_in[2];
    const float* Wq    = (const float*)d_in[3];
    const float* bq    = (const float*)d_in[4];
    const float* Wk    = (const float*)d_in[5];
    const float* bk    = (const float*)d_in[6];
    const float* Wv    = (const float*)d_in[7];
    const float* bv    = (const float*)d_in[8];
    const float* Er    = (const float*)d_in[9];
    const float* W1    = (const float*)d_in[10];
    const float* b1    = (const float*)d_in[11];
    const float* W2    = (const float*)d_in[12];
    const float* b2    = (const float*)d_in[13];
    const float* We    = (const float*)d_in[14];
    const float* be    = (const float*)d_in[15];
    float* out = (float*)d_out;

    cudaFuncSetAttribute(attn_ffn_kernel,
                         cudaFuncAttributeMaxDynamicSharedMemorySize,
                         SMEM_FLOATS * 4);

    attn_ffn_kernel<<<NTOK, 256, SMEM_FLOATS * 4>>>(
        x, Wq, bq, Wk, bk, Wv, bv, Er, W1, b1, W2, b2);

    dim3 g2(EMBc / GBN, NTOK / GBM);   // (4, 32) = 128 blocks
    we_gemm_kernel<<<g2, 256>>>(We, be);

    stats_kernel<<<1, 32>>>();

    final_kernel<<<NTOK, 256>>>(o_enc, r_enc, out);
}